// round 4
// baseline (speedup 1.0000x reference)
#include <cuda_runtime.h>
#include <cuda_bf16.h>
#include <cuda_fp16.h>
#include <cstdint>
#include <cfloat>

// Problem dims (fixed per reference)
#define N_SAMPLES 131072
#define N_CENT    2048
#define DIM       256

// ---------------- scratch (static device globals; no runtime alloc) ----------------
__device__ __nv_bfloat16 g_xb[(size_t)N_SAMPLES * DIM];     // x in bf16 (64 MB)
__device__ __nv_bfloat16 g_cb[(size_t)N_CENT * DIM];        // centroids bf16 (1 MB)
__device__ float         g_csq[N_CENT];                      // ||c||^2 fp32
__device__ __half        g_dots[(size_t)N_SAMPLES * N_CENT]; // x.c fp16 (536 MB)
__device__ float         g_sums[(size_t)N_CENT * DIM];       // scatter sums
__device__ int           g_counts[N_CENT];

// ---------------- K0: zero sums + counts ----------------
__global__ void k_zero() {
    int i = blockIdx.x * blockDim.x + threadIdx.x;
    int total = N_CENT * DIM;
    if (i < total) g_sums[i] = 0.0f;
    if (i < N_CENT) g_counts[i] = 0;
}

// ---------------- K1a: convert x -> bf16 (float4 granular) ----------------
__global__ void k_convert_x(const float* __restrict__ x) {
    size_t i = (size_t)blockIdx.x * blockDim.x + threadIdx.x;  // over float4s
    const size_t n4 = (size_t)N_SAMPLES * DIM / 4;
    if (i >= n4) return;
    float4 v = reinterpret_cast<const float4*>(x)[i];
    __nv_bfloat162 p0 = __nv_bfloat162(__float2bfloat16(v.x), __float2bfloat16(v.y));
    __nv_bfloat162 p1 = __nv_bfloat162(__float2bfloat16(v.z), __float2bfloat16(v.w));
    *reinterpret_cast<__nv_bfloat162*>(g_xb + i * 4)     = p0;
    *reinterpret_cast<__nv_bfloat162*>(g_xb + i * 4 + 2) = p1;
}

// ---------------- K1b: centroids -> bf16 + csq (warp per centroid) ----------------
__global__ void k_convert_c(const float* __restrict__ c) {
    int warp = (blockIdx.x * blockDim.x + threadIdx.x) / 32;
    int lane = threadIdx.x & 31;
    if (warp >= N_CENT) return;
    const float* row = c + (size_t)warp * DIM + lane * 8;
    float4 a = *reinterpret_cast<const float4*>(row);
    float4 b = *reinterpret_cast<const float4*>(row + 4);
    __nv_bfloat16* dst = g_cb + (size_t)warp * DIM + lane * 8;
    dst[0] = __float2bfloat16(a.x); dst[1] = __float2bfloat16(a.y);
    dst[2] = __float2bfloat16(a.z); dst[3] = __float2bfloat16(a.w);
    dst[4] = __float2bfloat16(b.x); dst[5] = __float2bfloat16(b.y);
    dst[6] = __float2bfloat16(b.z); dst[7] = __float2bfloat16(b.w);
    float s = a.x*a.x + a.y*a.y + a.z*a.z + a.w*a.w
            + b.x*b.x + b.y*b.y + b.z*b.z + b.w*b.w;
    #pragma unroll
    for (int off = 16; off; off >>= 1) s += __shfl_xor_sync(0xffffffffu, s, off);
    if (lane == 0) g_csq[warp] = s;
}

// ---------------- K2: bf16 MMA GEMM: dots[n][k] = sum_d xb[n,d]*cb[k,d] ----------------
// Tile: BM=128, BN=128, BK=32. 8 warps: 4 along M x 2 along N; warp tile 32x64.
#define BM 128
#define BN 128
#define BK 32
#define SSTRIDE 40   // halfs; 80B rows -> 16B aligned + conflict-free frag loads

__global__ __launch_bounds__(256, 2) void k_gemm() {
    __shared__ __nv_bfloat16 sA[BM * SSTRIDE];
    __shared__ __nv_bfloat16 sB[BN * SSTRIDE];

    const int tid  = threadIdx.x;
    const int warp = tid >> 5, lane = tid & 31;
    const int wm = warp & 3, wn = warp >> 2;
    const int g  = lane >> 2, t4 = lane & 3;
    const int rowBase = blockIdx.x * BM;
    const int colBase = blockIdx.y * BN;

    float acc[2][8][4];
    #pragma unroll
    for (int a = 0; a < 2; a++)
        #pragma unroll
        for (int b = 0; b < 8; b++)
            #pragma unroll
            for (int c = 0; c < 4; c++) acc[a][b][c] = 0.0f;

    for (int k0 = 0; k0 < DIM; k0 += BK) {
        // cooperative tile load: 512 uint4 per tile, 256 threads x 2
        #pragma unroll
        for (int it = 0; it < 2; it++) {
            int i = tid + it * 256;           // 0..511
            int r = i >> 2;
            int cc = (i & 3) * 8;             // half offset within BK
            uint4 va = *reinterpret_cast<const uint4*>(g_xb + (size_t)(rowBase + r) * DIM + k0 + cc);
            *reinterpret_cast<uint4*>(sA + r * SSTRIDE + cc) = va;
            uint4 vb = *reinterpret_cast<const uint4*>(g_cb + (size_t)(colBase + r) * DIM + k0 + cc);
            *reinterpret_cast<uint4*>(sB + r * SSTRIDE + cc) = vb;
        }
        __syncthreads();

        #pragma unroll
        for (int kk = 0; kk < BK; kk += 16) {
            uint32_t af[2][4];
            #pragma unroll
            for (int mi = 0; mi < 2; mi++) {
                int r = wm * 32 + mi * 16 + g;
                af[mi][0] = *reinterpret_cast<const uint32_t*>(sA + r * SSTRIDE + kk + t4 * 2);
                af[mi][1] = *reinterpret_cast<const uint32_t*>(sA + (r + 8) * SSTRIDE + kk + t4 * 2);
                af[mi][2] = *reinterpret_cast<const uint32_t*>(sA + r * SSTRIDE + kk + t4 * 2 + 8);
                af[mi][3] = *reinterpret_cast<const uint32_t*>(sA + (r + 8) * SSTRIDE + kk + t4 * 2 + 8);
            }
            uint32_t bf[8][2];
            #pragma unroll
            for (int ni = 0; ni < 8; ni++) {
                int n = wn * 64 + ni * 8 + g;
                bf[ni][0] = *reinterpret_cast<const uint32_t*>(sB + n * SSTRIDE + kk + t4 * 2);
                bf[ni][1] = *reinterpret_cast<const uint32_t*>(sB + n * SSTRIDE + kk + t4 * 2 + 8);
            }
            #pragma unroll
            for (int mi = 0; mi < 2; mi++)
                #pragma unroll
                for (int ni = 0; ni < 8; ni++) {
                    asm volatile(
                        "mma.sync.aligned.m16n8k16.row.col.f32.bf16.bf16.f32 "
                        "{%0,%1,%2,%3}, {%4,%5,%6,%7}, {%8,%9}, {%0,%1,%2,%3};\n"
                        : "+f"(acc[mi][ni][0]), "+f"(acc[mi][ni][1]),
                          "+f"(acc[mi][ni][2]), "+f"(acc[mi][ni][3])
                        : "r"(af[mi][0]), "r"(af[mi][1]), "r"(af[mi][2]), "r"(af[mi][3]),
                          "r"(bf[ni][0]), "r"(bf[ni][1]));
                }
        }
        __syncthreads();
    }

    // epilogue: store fp16 dots
    #pragma unroll
    for (int mi = 0; mi < 2; mi++) {
        #pragma unroll
        for (int ni = 0; ni < 8; ni++) {
            size_t r = (size_t)(rowBase + wm * 32 + mi * 16 + g);
            size_t c = (size_t)(colBase + wn * 64 + ni * 8 + t4 * 2);
            *reinterpret_cast<__half2*>(g_dots + r * N_CENT + c) =
                __floats2half2_rn(acc[mi][ni][0], acc[mi][ni][1]);
            *reinterpret_cast<__half2*>(g_dots + (r + 8) * N_CENT + c) =
                __floats2half2_rn(acc[mi][ni][2], acc[mi][ni][3]);
        }
    }
}

// ---------------- K3: argmin + exact rescore + fused scatter ----------------
// Block = 128 threads (4 warps), warp per sample row. Grid = 131072/4.
#define MARGIN 4.0f

__global__ __launch_bounds__(128) void k_assign(const float* __restrict__ x,
                                                const float* __restrict__ cent) {
    __shared__ float s_csq[N_CENT];
    __shared__ float s_x[4][DIM];

    const int tid = threadIdx.x;
    const int warp = tid >> 5, lane = tid & 31;

    // load csq
    #pragma unroll
    for (int i = 0; i < N_CENT / 128; i++) s_csq[tid + i * 128] = g_csq[tid + i * 128];
    __syncthreads();

    const int row = blockIdx.x * 4 + warp;

    // x row -> smem (fp32)
    {
        const float* xr = x + (size_t)row * DIM + lane * 8;
        float4 a = *reinterpret_cast<const float4*>(xr);
        float4 b = *reinterpret_cast<const float4*>(xr + 4);
        *reinterpret_cast<float4*>(&s_x[warp][lane * 8])     = a;
        *reinterpret_cast<float4*>(&s_x[warp][lane * 8 + 4]) = b;
    }
    __syncwarp();

    // load 2048 fp16 dots, coalesced: lane l, chunk j -> ks = j*256 + l*8 + e
    uint4 dv[8];
    const __half* drow = g_dots + (size_t)row * N_CENT;
    #pragma unroll
    for (int j = 0; j < 8; j++)
        dv[j] = *reinterpret_cast<const uint4*>(drow + j * 256 + lane * 8);

    // approximate min over this lane's 64 scores
    float mn = FLT_MAX;
    #pragma unroll
    for (int j = 0; j < 8; j++) {
        const uint32_t* w = reinterpret_cast<const uint32_t*>(&dv[j]);
        #pragma unroll
        for (int q = 0; q < 4; q++) {
            __half2 h2 = *reinterpret_cast<const __half2*>(&w[q]);
            float d0 = __low2float(h2), d1 = __high2float(h2);
            int k0 = j * 256 + lane * 8 + q * 2;
            float sc0 = s_csq[k0]     - 2.0f * d0;
            float sc1 = s_csq[k0 + 1] - 2.0f * d1;
            mn = fminf(mn, fminf(sc0, sc1));
        }
    }
    #pragma unroll
    for (int off = 16; off; off >>= 1) mn = fminf(mn, __shfl_xor_sync(0xffffffffu, mn, off));
    const float thresh = mn + MARGIN;

    // exact (double) rescore of candidates
    double bestS = DBL_MAX;
    int bestK = 0x7fffffff;
    const float* xs = s_x[warp];
    #pragma unroll
    for (int j = 0; j < 8; j++) {
        const uint32_t* w = reinterpret_cast<const uint32_t*>(&dv[j]);
        #pragma unroll
        for (int q = 0; q < 4; q++) {
            __half2 h2 = *reinterpret_cast<const __half2*>(&w[q]);
            float dd[2] = { __low2float(h2), __high2float(h2) };
            #pragma unroll
            for (int e = 0; e < 2; e++) {
                int k = j * 256 + lane * 8 + q * 2 + e;
                float sc = s_csq[k] - 2.0f * dd[e];
                if (sc <= thresh) {
                    const float* crow = cent + (size_t)k * DIM;
                    double dot = 0.0, cs = 0.0;
                    for (int d = 0; d < DIM; d++) {
                        double cv = (double)crow[d];
                        dot += (double)xs[d] * cv;
                        cs  += cv * cv;
                    }
                    double s = cs - 2.0 * dot;
                    if (s < bestS || (s == bestS && k < bestK)) { bestS = s; bestK = k; }
                }
            }
        }
    }
    // warp reduce (min score, then min index) — matches argmin first-occurrence
    #pragma unroll
    for (int off = 16; off; off >>= 1) {
        double os = __shfl_xor_sync(0xffffffffu, bestS, off);
        int   ok = __shfl_xor_sync(0xffffffffu, bestK, off);
        if (os < bestS || (os == bestS && ok < bestK)) { bestS = os; bestK = ok; }
    }
    const int kstar = __shfl_sync(0xffffffffu, bestK, 0);

    // fused scatter: count + vector reduction of x row into sums
    if (lane == 0) atomicAdd(&g_counts[kstar], 1);
    float* dst = g_sums + (size_t)kstar * DIM + lane * 8;
    float4 v0 = *reinterpret_cast<const float4*>(&s_x[warp][lane * 8]);
    float4 v1 = *reinterpret_cast<const float4*>(&s_x[warp][lane * 8 + 4]);
    asm volatile("red.global.add.v4.f32 [%0], {%1,%2,%3,%4};\n"
                 :: "l"(dst), "f"(v0.x), "f"(v0.y), "f"(v0.z), "f"(v0.w) : "memory");
    asm volatile("red.global.add.v4.f32 [%0], {%1,%2,%3,%4};\n"
                 :: "l"(dst + 4), "f"(v1.x), "f"(v1.y), "f"(v1.z), "f"(v1.w) : "memory");
}

// ---------------- K4: finalize ----------------
__global__ void k_finalize(const float* __restrict__ cent, float* __restrict__ out) {
    int i = blockIdx.x * blockDim.x + threadIdx.x;
    if (i >= N_CENT * DIM) return;
    int k = i >> 8;  // /256
    int cnt = g_counts[k];
    out[i] = (cnt > 0) ? (g_sums[i] / (float)cnt) : cent[i];
}

// ---------------- launcher ----------------
extern "C" void kernel_launch(void* const* d_in, const int* in_sizes, int n_in,
                              void* d_out, int out_size) {
    const float* x    = (const float*)d_in[0];   // (131072, 256)
    const float* cent = (const float*)d_in[1];   // (2048, 256)
    float* out = (float*)d_out;                  // (2048, 256)

    k_zero<<<(N_CENT * DIM + 255) / 256, 256>>>();
    k_convert_x<<<(N_SAMPLES * DIM / 4 + 255) / 256, 256>>>(x);
    k_convert_c<<<N_CENT * 32 / 256, 256>>>(cent);

    dim3 gg(N_SAMPLES / BM, N_CENT / BN);
    k_gemm<<<gg, 256>>>();

    k_assign<<<N_SAMPLES / 4, 128>>>(x, cent);

    k_finalize<<<(N_CENT * DIM + 255) / 256, 256>>>(cent, out);
}

// round 7
// speedup vs baseline: 29.9449x; 29.9449x over previous
#include <cuda_runtime.h>
#include <cuda_bf16.h>
#include <cuda_fp16.h>
#include <cstdint>
#include <cfloat>
#include <climits>

// Problem dims (fixed per reference)
#define N_SAMPLES 131072
#define N_CENT    2048
#define DIM       256

// ---------------- scratch (static device globals; no runtime alloc) ----------------
__device__ __nv_bfloat16 g_xb[(size_t)N_SAMPLES * DIM];     // x in bf16 (64 MB)
__device__ __nv_bfloat16 g_cb[(size_t)N_CENT * DIM];        // centroids bf16 (1 MB)
__device__ float         g_csq[N_CENT];                      // ||c||^2 fp32
__device__ __half        g_dots[(size_t)N_SAMPLES * N_CENT]; // x.c fp16 (536 MB)
__device__ float         g_sums[(size_t)N_CENT * DIM];       // scatter sums
__device__ int           g_counts[N_CENT];

// ---------------- K0: zero sums + counts ----------------
__global__ void k_zero() {
    int i = blockIdx.x * blockDim.x + threadIdx.x;
    int total = N_CENT * DIM;
    if (i < total) g_sums[i] = 0.0f;
    if (i < N_CENT) g_counts[i] = 0;
}

// ---------------- K1a: convert x -> bf16 (float4 granular) ----------------
__global__ void k_convert_x(const float* __restrict__ x) {
    size_t i = (size_t)blockIdx.x * blockDim.x + threadIdx.x;  // over float4s
    const size_t n4 = (size_t)N_SAMPLES * DIM / 4;
    if (i >= n4) return;
    float4 v = reinterpret_cast<const float4*>(x)[i];
    __nv_bfloat162 p0 = __nv_bfloat162(__float2bfloat16(v.x), __float2bfloat16(v.y));
    __nv_bfloat162 p1 = __nv_bfloat162(__float2bfloat16(v.z), __float2bfloat16(v.w));
    *reinterpret_cast<__nv_bfloat162*>(g_xb + i * 4)     = p0;
    *reinterpret_cast<__nv_bfloat162*>(g_xb + i * 4 + 2) = p1;
}

// ---------------- K1b: centroids -> bf16 + csq (warp per centroid) ----------------
__global__ void k_convert_c(const float* __restrict__ c) {
    int warp = (blockIdx.x * blockDim.x + threadIdx.x) / 32;
    int lane = threadIdx.x & 31;
    if (warp >= N_CENT) return;
    const float* row = c + (size_t)warp * DIM + lane * 8;
    float4 a = *reinterpret_cast<const float4*>(row);
    float4 b = *reinterpret_cast<const float4*>(row + 4);
    __nv_bfloat16* dst = g_cb + (size_t)warp * DIM + lane * 8;
    dst[0] = __float2bfloat16(a.x); dst[1] = __float2bfloat16(a.y);
    dst[2] = __float2bfloat16(a.z); dst[3] = __float2bfloat16(a.w);
    dst[4] = __float2bfloat16(b.x); dst[5] = __float2bfloat16(b.y);
    dst[6] = __float2bfloat16(b.z); dst[7] = __float2bfloat16(b.w);
    float s = a.x*a.x + a.y*a.y + a.z*a.z + a.w*a.w
            + b.x*b.x + b.y*b.y + b.z*b.z + b.w*b.w;
    #pragma unroll
    for (int off = 16; off; off >>= 1) s += __shfl_xor_sync(0xffffffffu, s, off);
    if (lane == 0) g_csq[warp] = s;
}

// ---------------- K2: bf16 MMA GEMM, cp.async double-buffered ----------------
// Tile: BM=128, BN=128, BK=32. 8 warps: 4 along M x 2 along N; warp tile 32x64.
#define BM 128
#define BN 128
#define BK 32
#define SSTRIDE 40   // halfs; 80B rows -> 16B aligned + conflict-free frag loads
#define KTILES (DIM / BK)   // 8

__device__ __forceinline__ void cp_async16(uint32_t smem_addr, const void* gptr) {
    asm volatile("cp.async.cg.shared.global [%0], [%1], 16;\n"
                 :: "r"(smem_addr), "l"(gptr));
}

__global__ __launch_bounds__(256, 2) void k_gemm() {
    __shared__ __nv_bfloat16 sA[2][BM * SSTRIDE];
    __shared__ __nv_bfloat16 sB[2][BN * SSTRIDE];

    const int tid  = threadIdx.x;
    const int warp = tid >> 5, lane = tid & 31;
    const int wm = warp & 3, wn = warp >> 2;
    const int g  = lane >> 2, t4 = lane & 3;
    const int rowBase = blockIdx.x * BM;
    const int colBase = blockIdx.y * BN;

    // per-thread load coords (2 x uint4 per matrix per stage)
    const int r0 = tid >> 2;               // 0..63
    const int r1 = r0 + 64;                // 64..127
    const int cc = (tid & 3) * 8;          // half offset within BK

    float acc[2][8][4];
    #pragma unroll
    for (int a = 0; a < 2; a++)
        #pragma unroll
        for (int b = 0; b < 8; b++)
            #pragma unroll
            for (int c = 0; c < 4; c++) acc[a][b][c] = 0.0f;

    auto load_stage = [&](int buf, int k0) {
        uint32_t a0 = (uint32_t)__cvta_generic_to_shared(sA[buf] + r0 * SSTRIDE + cc);
        uint32_t a1 = (uint32_t)__cvta_generic_to_shared(sA[buf] + r1 * SSTRIDE + cc);
        uint32_t b0 = (uint32_t)__cvta_generic_to_shared(sB[buf] + r0 * SSTRIDE + cc);
        uint32_t b1 = (uint32_t)__cvta_generic_to_shared(sB[buf] + r1 * SSTRIDE + cc);
        cp_async16(a0, g_xb + (size_t)(rowBase + r0) * DIM + k0 + cc);
        cp_async16(a1, g_xb + (size_t)(rowBase + r1) * DIM + k0 + cc);
        cp_async16(b0, g_cb + (size_t)(colBase + r0) * DIM + k0 + cc);
        cp_async16(b1, g_cb + (size_t)(colBase + r1) * DIM + k0 + cc);
    };

    load_stage(0, 0);
    asm volatile("cp.async.commit_group;\n" ::: "memory");

    for (int kt = 0; kt < KTILES; kt++) {
        const int buf = kt & 1;
        if (kt + 1 < KTILES) {
            load_stage((kt + 1) & 1, (kt + 1) * BK);
            asm volatile("cp.async.commit_group;\n" ::: "memory");
            asm volatile("cp.async.wait_group 1;\n" ::: "memory");
        } else {
            asm volatile("cp.async.wait_group 0;\n" ::: "memory");
        }
        __syncthreads();

        const __nv_bfloat16* cA = sA[buf];
        const __nv_bfloat16* cB = sB[buf];
        #pragma unroll
        for (int kk = 0; kk < BK; kk += 16) {
            uint32_t af[2][4];
            #pragma unroll
            for (int mi = 0; mi < 2; mi++) {
                int r = wm * 32 + mi * 16 + g;
                af[mi][0] = *reinterpret_cast<const uint32_t*>(cA + r * SSTRIDE + kk + t4 * 2);
                af[mi][1] = *reinterpret_cast<const uint32_t*>(cA + (r + 8) * SSTRIDE + kk + t4 * 2);
                af[mi][2] = *reinterpret_cast<const uint32_t*>(cA + r * SSTRIDE + kk + t4 * 2 + 8);
                af[mi][3] = *reinterpret_cast<const uint32_t*>(cA + (r + 8) * SSTRIDE + kk + t4 * 2 + 8);
            }
            uint32_t bfr[8][2];
            #pragma unroll
            for (int ni = 0; ni < 8; ni++) {
                int n = wn * 64 + ni * 8 + g;
                bfr[ni][0] = *reinterpret_cast<const uint32_t*>(cB + n * SSTRIDE + kk + t4 * 2);
                bfr[ni][1] = *reinterpret_cast<const uint32_t*>(cB + n * SSTRIDE + kk + t4 * 2 + 8);
            }
            #pragma unroll
            for (int mi = 0; mi < 2; mi++)
                #pragma unroll
                for (int ni = 0; ni < 8; ni++) {
                    asm volatile(
                        "mma.sync.aligned.m16n8k16.row.col.f32.bf16.bf16.f32 "
                        "{%0,%1,%2,%3}, {%4,%5,%6,%7}, {%8,%9}, {%0,%1,%2,%3};\n"
                        : "+f"(acc[mi][ni][0]), "+f"(acc[mi][ni][1]),
                          "+f"(acc[mi][ni][2]), "+f"(acc[mi][ni][3])
                        : "r"(af[mi][0]), "r"(af[mi][1]), "r"(af[mi][2]), "r"(af[mi][3]),
                          "r"(bfr[ni][0]), "r"(bfr[ni][1]));
                }
        }
        __syncthreads();
    }

    // epilogue: store fp16 dots
    #pragma unroll
    for (int mi = 0; mi < 2; mi++) {
        #pragma unroll
        for (int ni = 0; ni < 8; ni++) {
            size_t r = (size_t)(rowBase + wm * 32 + mi * 16 + g);
            size_t c = (size_t)(colBase + wn * 64 + ni * 8 + t4 * 2);
            *reinterpret_cast<__half2*>(g_dots + r * N_CENT + c) =
                __floats2half2_rn(acc[mi][ni][0], acc[mi][ni][1]);
            *reinterpret_cast<__half2*>(g_dots + (r + 8) * N_CENT + c) =
                __floats2half2_rn(acc[mi][ni][2], acc[mi][ni][3]);
        }
    }
}

// ---------------- K3: argmin + warp-cooperative exact rescore + fused scatter ----------------
// Block = 256 threads (8 warps), warp per sample row. Grid = 131072/8.
#define MARGIN 3.0f
#define MAXCAND 32

__global__ __launch_bounds__(256) void k_assign(const float* __restrict__ x,
                                                const float* __restrict__ cent) {
    __shared__ float s_csq[N_CENT];
    __shared__ float s_x[8][DIM];
    __shared__ int   s_cand[8][MAXCAND];
    __shared__ int   s_cnt[8];

    const int tid = threadIdx.x;
    const int warp = tid >> 5, lane = tid & 31;

    // load csq (8 KB, L2-resident)
    #pragma unroll
    for (int i = 0; i < N_CENT / 256; i++) s_csq[tid + i * 256] = g_csq[tid + i * 256];
    if (lane == 0) s_cnt[warp] = 0;
    __syncthreads();

    const int row = blockIdx.x * 8 + warp;

    // x row -> smem (fp32)
    {
        const float* xr = x + (size_t)row * DIM + lane * 8;
        float4 a = *reinterpret_cast<const float4*>(xr);
        float4 b = *reinterpret_cast<const float4*>(xr + 4);
        *reinterpret_cast<float4*>(&s_x[warp][lane * 8])     = a;
        *reinterpret_cast<float4*>(&s_x[warp][lane * 8 + 4]) = b;
    }

    // load 2048 fp16 dots, coalesced: lane l, chunk j -> k = j*256 + l*8 + e
    uint4 dv[8];
    const __half* drow = g_dots + (size_t)row * N_CENT;
    #pragma unroll
    for (int j = 0; j < 8; j++)
        dv[j] = *reinterpret_cast<const uint4*>(drow + j * 256 + lane * 8);

    // pass 1: approximate min over this lane's 64 scores
    float mn = FLT_MAX;
    #pragma unroll
    for (int j = 0; j < 8; j++) {
        const uint32_t* w = reinterpret_cast<const uint32_t*>(&dv[j]);
        #pragma unroll
        for (int q = 0; q < 4; q++) {
            __half2 h2 = *reinterpret_cast<const __half2*>(&w[q]);
            float d0 = __low2float(h2), d1 = __high2float(h2);
            int k0 = j * 256 + lane * 8 + q * 2;
            float sc0 = s_csq[k0]     - 2.0f * d0;
            float sc1 = s_csq[k0 + 1] - 2.0f * d1;
            mn = fminf(mn, fminf(sc0, sc1));
        }
    }
    #pragma unroll
    for (int off = 16; off; off >>= 1) mn = fminf(mn, __shfl_xor_sync(0xffffffffu, mn, off));
    const float thresh = mn + MARGIN;

    // pass 2: collect candidate indices into shared per-warp list
    #pragma unroll
    for (int j = 0; j < 8; j++) {
        const uint32_t* w = reinterpret_cast<const uint32_t*>(&dv[j]);
        #pragma unroll
        for (int q = 0; q < 4; q++) {
            __half2 h2 = *reinterpret_cast<const __half2*>(&w[q]);
            float dd[2] = { __low2float(h2), __high2float(h2) };
            #pragma unroll
            for (int e = 0; e < 2; e++) {
                int k = j * 256 + lane * 8 + q * 2 + e;
                float sc = s_csq[k] - 2.0f * dd[e];
                if (sc <= thresh) {
                    int p = atomicAdd(&s_cnt[warp], 1);
                    if (p < MAXCAND) s_cand[warp][p] = k;
                }
            }
        }
    }
    __syncwarp();
    int cnt = s_cnt[warp];
    if (cnt > MAXCAND) cnt = MAXCAND;

    // warp-cooperative exact (double) rescore: lane handles 8 dims per candidate
    double bestS = DBL_MAX;
    int bestK = INT_MAX;
    const float* xp = &s_x[warp][lane * 8];
    for (int ci = 0; ci < cnt; ci++) {
        int k = s_cand[warp][ci];
        const float* crow = cent + (size_t)k * DIM + lane * 8;
        float4 c0 = *reinterpret_cast<const float4*>(crow);
        float4 c1 = *reinterpret_cast<const float4*>(crow + 4);
        double dot = 0.0, cs = 0.0, cv;
        cv = (double)c0.x; dot += cv * (double)xp[0]; cs += cv * cv;
        cv = (double)c0.y; dot += cv * (double)xp[1]; cs += cv * cv;
        cv = (double)c0.z; dot += cv * (double)xp[2]; cs += cv * cv;
        cv = (double)c0.w; dot += cv * (double)xp[3]; cs += cv * cv;
        cv = (double)c1.x; dot += cv * (double)xp[4]; cs += cv * cv;
        cv = (double)c1.y; dot += cv * (double)xp[5]; cs += cv * cv;
        cv = (double)c1.z; dot += cv * (double)xp[6]; cs += cv * cv;
        cv = (double)c1.w; dot += cv * (double)xp[7]; cs += cv * cv;
        #pragma unroll
        for (int off = 16; off; off >>= 1) {
            dot += __shfl_xor_sync(0xffffffffu, dot, off);
            cs  += __shfl_xor_sync(0xffffffffu, cs,  off);
        }
        double s = cs - 2.0 * dot;
        if (s < bestS || (s == bestS && k < bestK)) { bestS = s; bestK = k; }
    }
    const int kstar = bestK;  // identical across lanes (butterfly reduce)

    // fused scatter: count + vector reduction of x row into sums
    if (lane == 0) atomicAdd(&g_counts[kstar], 1);
    float* dst = g_sums + (size_t)kstar * DIM + lane * 8;
    float4 v0 = *reinterpret_cast<const float4*>(&s_x[warp][lane * 8]);
    float4 v1 = *reinterpret_cast<const float4*>(&s_x[warp][lane * 8 + 4]);
    asm volatile("red.global.add.v4.f32 [%0], {%1,%2,%3,%4};\n"
                 :: "l"(dst), "f"(v0.x), "f"(v0.y), "f"(v0.z), "f"(v0.w) : "memory");
    asm volatile("red.global.add.v4.f32 [%0], {%1,%2,%3,%4};\n"
                 :: "l"(dst + 4), "f"(v1.x), "f"(v1.y), "f"(v1.z), "f"(v1.w) : "memory");
}

// ---------------- K4: finalize ----------------
__global__ void k_finalize(const float* __restrict__ cent, float* __restrict__ out) {
    int i = blockIdx.x * blockDim.x + threadIdx.x;
    if (i >= N_CENT * DIM) return;
    int k = i >> 8;  // /256
    int cnt = g_counts[k];
    out[i] = (cnt > 0) ? (g_sums[i] / (float)cnt) : cent[i];
}

// ---------------- launcher ----------------
extern "C" void kernel_launch(void* const* d_in, const int* in_sizes, int n_in,
                              void* d_out, int out_size) {
    const float* x    = (const float*)d_in[0];   // (131072, 256)
    const float* cent = (const float*)d_in[1];   // (2048, 256)
    float* out = (float*)d_out;                  // (2048, 256)

    k_zero<<<(N_CENT * DIM + 255) / 256, 256>>>();
    k_convert_x<<<(N_SAMPLES * DIM / 4 + 255) / 256, 256>>>(x);
    k_convert_c<<<N_CENT * 32 / 256, 256>>>(cent);

    dim3 gg(N_SAMPLES / BM, N_CENT / BN);
    k_gemm<<<gg, 256>>>();

    k_assign<<<N_SAMPLES / 8, 256>>>(x, cent);

    k_finalize<<<(N_CENT * DIM + 255) / 256, 256>>>(cent, out);
}